// round 15
// baseline (speedup 1.0000x reference)
#include <cuda_runtime.h>
#include <cuda_fp16.h>
#include <cuda_bf16.h>
#include <cstdint>

#define S1 4097
#define SMAX 4096
#define DM 160
#define NH 4
#define HD 40
#define BATCH 4
#define KT 64
#define NTK 65           // ceil(4097/64)
#define NROWS (BATCH * S1)
#define L2E 1.4426950408889634f
#define KP_TILE 1536     // u32 per K fragment tile (3kt*4j*32lane*4) bf16x2
#define VP_TILE 1536     // u32 per V fragment tile (4kt*3j*32lane*4) f16x2

// ---------------- device scratch ----------------
__device__ float g_f[BATCH * S1 * DM];
__device__ float g_q[BATCH * NH * S1 * HD];
__device__ float g_k[BATCH * NH * S1 * HD];
__device__ float g_v[BATCH * NH * S1 * HD];
__device__ float g_att[BATCH * NH * S1 * HD];
__device__ float g_stats[BATCH * SMAX * 2];
__device__ uint32_t g_kp[BATCH * NH * NTK * KP_TILE];   // K in bf16 B-frag order
__device__ uint32_t g_vp[BATCH * NH * NTK * VP_TILE];   // V in f16 B-frag order
__device__ uint4    g_wp[3 * 6400];                     // qkv weights, tf32 B-frag order

// ---------------- helpers ----------------
__device__ __forceinline__ void mma_bf16(float* c, const uint32_t* a, uint32_t b0, uint32_t b1) {
    asm volatile(
        "mma.sync.aligned.m16n8k16.row.col.f32.bf16.bf16.f32 "
        "{%0,%1,%2,%3}, {%4,%5,%6,%7}, {%8,%9}, {%0,%1,%2,%3};"
        : "+f"(c[0]), "+f"(c[1]), "+f"(c[2]), "+f"(c[3])
        : "r"(a[0]), "r"(a[1]), "r"(a[2]), "r"(a[3]), "r"(b0), "r"(b1));
}
__device__ __forceinline__ void mma_tf32(float* c, const uint32_t* a, uint32_t b0, uint32_t b1) {
    asm volatile(
        "mma.sync.aligned.m16n8k8.row.col.f32.tf32.tf32.f32 "
        "{%0,%1,%2,%3}, {%4,%5,%6,%7}, {%8,%9}, {%0,%1,%2,%3};"
        : "+f"(c[0]), "+f"(c[1]), "+f"(c[2]), "+f"(c[3])
        : "r"(a[0]), "r"(a[1]), "r"(a[2]), "r"(a[3]), "r"(b0), "r"(b1));
}
__device__ __forceinline__ void mma_f16(float* c, const uint32_t* a, const uint32_t* b) {
    asm volatile(
        "mma.sync.aligned.m16n8k16.row.col.f32.f16.f16.f32 "
        "{%0,%1,%2,%3}, {%4,%5,%6,%7}, {%8,%9}, {%0,%1,%2,%3};"
        : "+f"(c[0]), "+f"(c[1]), "+f"(c[2]), "+f"(c[3])
        : "r"(a[0]), "r"(a[1]), "r"(a[2]), "r"(a[3]), "r"(b[0]), "r"(b[1]));
}
__device__ __forceinline__ float to_tf32(float x) {
    float r;
    asm("cvt.rna.tf32.f32 %0, %1;" : "=f"(r) : "f"(x));
    return r;
}
__device__ __forceinline__ uint32_t pack_bf16x2(float lo, float hi) {
    uint32_t p;
    asm("cvt.rn.bf16x2.f32 %0, %1, %2;" : "=r"(p) : "f"(hi), "f"(lo));
    return p;
}
__device__ __forceinline__ uint32_t pack_ex2_f16x2(float lo, float hi) {
    uint32_t p, r;
    asm("cvt.rn.f16x2.f32 %0, %1, %2;" : "=r"(p) : "f"(hi), "f"(lo));
    asm("ex2.approx.f16x2 %0, %1;" : "=r"(r) : "r"(p));
    return r;
}
__device__ __forceinline__ uint32_t pack_f16x2(float lo, float hi) {
    uint32_t p;
    asm("cvt.rn.f16x2.f32 %0, %1, %2;" : "=r"(p) : "f"(hi), "f"(lo));
    return p;
}
__device__ __forceinline__ uint32_t smem_u32(const void* p) {
    uint32_t a;
    asm("{ .reg .u64 t; cvta.to.shared.u64 t, %1; cvt.u32.u64 %0, t; }" : "=r"(a) : "l"(p));
    return a;
}
#define CP_ASYNC16(sdst, gsrc) \
    asm volatile("cp.async.cg.shared.global [%0], [%1], 16;" :: "r"(sdst), "l"(gsrc))
#define CP_COMMIT() asm volatile("cp.async.commit_group;")
#define CP_WAIT0()  asm volatile("cp.async.wait_group 0;")
#define CP_WAIT1()  asm volatile("cp.async.wait_group 1;")

// ================= wprep: qkv weights -> tf32 B-fragment order ==============
__global__ void __launch_bounds__(256) k_wprep(const float* __restrict__ wq,
                                               const float* __restrict__ wk,
                                               const float* __restrict__ wv)
{
    int mat = blockIdx.x;
    const float* w = (mat == 0) ? wq : ((mat == 1) ? wk : wv);
    for (int idx = threadIdx.x; idx < 6400; idx += 256) {
        int lane = idx & 31, rest = idx >> 5;
        int ntp = rest % 10, kt = rest / 10;
        int g = lane >> 2, tg = lane & 3;
        uint4 val;
        uint32_t* vv = (uint32_t*)&val;
        #pragma unroll
        for (int e = 0; e < 4; e++) {
            int nt = 2 * ntp + (e >> 1), reg = e & 1;
            int n = g + 8 * nt;
            int kcol = 8 * kt + tg + 4 * reg;
            vv[e] = __float_as_uint(to_tf32(w[n * DM + kcol]));
        }
        g_wp[mat * 6400 + idx] = val;
    }
}

// ================= QKV v4c: tf32 mma, 3-stage cp.async ring =================
// grid (129, 3), 256 threads (8 warps x 16 rows = 128 rows per CTA)
__global__ void __launch_bounds__(256, 2) k_qkv4()
{
    __shared__ uint4 wbuf[3][320];          // weight kt-chunk triple buffer (15 KB)

    const int tid = threadIdx.x, w = tid >> 5, lane = tid & 31;
    const int g = lane >> 2, tg = lane & 3;
    const int row0 = blockIdx.x * 128;
    const int mat = blockIdx.y;
    const uint4* wp = g_wp + mat * 6400;
    float* outp = (mat == 0) ? g_q : ((mat == 1) ? g_k : g_v);

    const int rA = row0 + w * 16 + g;       // global row; pair rA+8
    const int rB = rA + 8;
    const bool vA = rA < NROWS, vB = rB < NROWS;
    const float* fA = g_f + (size_t)rA * DM;
    const float* fB = g_f + (size_t)rB * DM;

    float acc[20][4];
    #pragma unroll
    for (int nt = 0; nt < 20; nt++)
        #pragma unroll
        for (int c = 0; c < 4; c++) acc[nt][c] = 0.f;

    uint32_t sw[3];
    sw[0] = smem_u32(&wbuf[0][0]);
    sw[1] = smem_u32(&wbuf[1][0]);
    sw[2] = smem_u32(&wbuf[2][0]);

    // prefetch chunks 0 and 1 (separate commit groups)
    #pragma unroll
    for (int c = 0; c < 2; c++) {
        const char* wg = (const char*)(wp + c * 320);
        CP_ASYNC16(sw[c] + tid * 16, wg + (size_t)tid * 16);
        if (tid < 64) CP_ASYNC16(sw[c] + (tid + 256) * 16, wg + (size_t)(tid + 256) * 16);
        CP_COMMIT();
    }

    // A fragment rotation
    uint32_t a_cur[4], a_nxt[4];
    {
        int c0 = tg, c1 = tg + 4;
        a_cur[0] = vA ? __float_as_uint(to_tf32(fA[c0])) : 0u;
        a_cur[1] = vB ? __float_as_uint(to_tf32(fB[c0])) : 0u;
        a_cur[2] = vA ? __float_as_uint(to_tf32(fA[c1])) : 0u;
        a_cur[3] = vB ? __float_as_uint(to_tf32(fB[c1])) : 0u;
    }

    for (int kt = 0; kt < 20; kt++) {
        CP_WAIT1();                         // chunk kt complete (1 pending allowed)
        __syncthreads();                    // also guards stage reuse
        if (kt + 2 < 20) {                  // prefetch kt+2 into stage (kt+2)%3
            uint32_t sd = sw[(kt + 2) % 3];
            const char* wg = (const char*)(wp + (kt + 2) * 320);
            CP_ASYNC16(sd + tid * 16, wg + (size_t)tid * 16);
            if (tid < 64) CP_ASYNC16(sd + (tid + 256) * 16, wg + (size_t)(tid + 256) * 16);
        }
        CP_COMMIT();                        // always commit (keeps pending-count invariant)
        if (kt + 1 < 20) {
            int c0 = 8 * (kt + 1) + tg, c1 = c0 + 4;
            a_nxt[0] = vA ? __float_as_uint(to_tf32(fA[c0])) : 0u;
            a_nxt[1] = vB ? __float_as_uint(to_tf32(fB[c0])) : 0u;
            a_nxt[2] = vA ? __float_as_uint(to_tf32(fA[c1])) : 0u;
            a_nxt[3] = vB ? __float_as_uint(to_tf32(fB[c1])) : 0u;
        }
        const uint4* wb = &wbuf[kt % 3][0];
        #pragma unroll
        for (int ntp = 0; ntp < 10; ntp++) {
            uint4 b = wb[ntp * 32 + lane];
            mma_tf32(acc[2 * ntp],     a_cur, b.x, b.y);
            mma_tf32(acc[2 * ntp + 1], a_cur, b.z, b.w);
        }
        a_cur[0] = a_nxt[0]; a_cur[1] = a_nxt[1];
        a_cur[2] = a_nxt[2]; a_cur[3] = a_nxt[3];
    }

    #pragma unroll
    for (int nt = 0; nt < 20; nt++) {
        int n0 = 8 * nt + 2 * tg;
        int h = n0 / HD, d = n0 % HD;
        if (vA) {
            int b = rA / S1, s = rA % S1;
            *(float2*)&outp[(((size_t)b * NH + h) * S1 + s) * HD + d] =
                make_float2(acc[nt][0], acc[nt][1]);
        }
        if (vB) {
            int b = rB / S1, s = rB % S1;
            *(float2*)&outp[(((size_t)b * NH + h) * S1 + s) * HD + d] =
                make_float2(acc[nt][2], acc[nt][3]);
        }
    }
}

// ================= prep: K(bf16)/V(f16) -> fragment-order scratch ===========
__global__ void __launch_bounds__(128) k_prep()
{
    int t = blockIdx.x, bh = blockIdx.y;
    int tid = threadIdx.x, lane = tid & 31, w = tid >> 5;
    int g = lane >> 2, tg = lane & 3;
    const float* kb = g_k + (size_t)bh * S1 * HD;
    const float* vb = g_v + (size_t)bh * S1 * HD;
    uint32_t* kp = g_kp + ((size_t)bh * NTK + t) * KP_TILE;
    uint32_t* vp = g_vp + ((size_t)bh * NTK + t) * VP_TILE;

    for (int c = w; c < 24; c += 4) {
        if (c < 12) {
            int kt = c >> 2, j = c & 3;
            uint4 val;
            uint32_t* vv = (uint32_t*)&val;
            #pragma unroll
            for (int e = 0; e < 4; e++) {
                int idx = j * 4 + e, nt = idx >> 1, reg = idx & 1;
                int key = t * KT + g + 8 * nt;
                int col = 16 * kt + 2 * (tg + 4 * reg);
                float v0 = (key < S1 && col     < HD) ? kb[(size_t)key * HD + col]     : 0.f;
                float v1 = (key < S1 && col + 1 < HD) ? kb[(size_t)key * HD + col + 1] : 0.f;
                vv[e] = pack_bf16x2(v0, v1);
            }
            ((uint4*)kp)[(kt * 4 + j) * 32 + lane] = val;
        } else {
            int cc = c - 12, kt = cc / 3, j = cc % 3;
            uint4 val;
            uint32_t* vv = (uint32_t*)&val;
            #pragma unroll
            for (int e = 0; e < 4; e++) {
                int idx = j * 4 + e, nt = idx >> 1, reg = idx & 1;
                int p = 8 * kt + tg + 4 * reg;
                int d = g + 8 * nt;
                uint32_t r;
                if (d == 40) r = 0x3C003C00u;
                else if (d > 40) r = 0u;
                else {
                    int k0 = t * KT + 2 * p;
                    float v0 = (k0     < S1) ? vb[(size_t)k0 * HD + d]       : 0.f;
                    float v1 = (k0 + 1 < S1) ? vb[(size_t)(k0 + 1) * HD + d] : 0.f;
                    r = pack_f16x2(v0, v1);
                }
                vv[e] = r;
            }
            ((uint4*)vp)[(kt * 3 + j) * 32 + lane] = val;
        }
    }
}

// ================= flash attention v5c (unchanged round-13/14) ==============
__global__ void __launch_bounds__(256, 2) k_flash5()
{
    __shared__ uint4 buf[2][768];

    const int tid = threadIdx.x, w = tid >> 5, lane = tid & 31;
    const int g = lane >> 2, tg = lane & 3;
    const int qt = blockIdx.x, bh = blockIdx.y;

    const float*    qb = g_q  + (size_t)bh * S1 * HD;
    const uint32_t* kp = g_kp + (size_t)bh * NTK * KP_TILE;
    const uint32_t* vp = g_vp + (size_t)bh * NTK * VP_TILE;

    const int r0 = qt * 128 + w * 16 + g;
    uint32_t qa[3][4];
    #pragma unroll
    for (int kt = 0; kt < 3; kt++) {
        int c0 = 16 * kt + 2 * tg;
        int c1 = c0 + 8;
        float q00 = (c0     < HD) ? qb[(size_t)r0 * HD + c0] * 0.158113883f : 0.f;
        float q01 = (c0 + 1 < HD) ? qb[(size_t)r0 * HD + c0 + 1] * 0.158113883f : 0.f;
        float q10 = (c0     < HD) ? qb[(size_t)(r0 + 8) * HD + c0] * 0.158113883f : 0.f;
        float q11 = (c0 + 1 < HD) ? qb[(size_t)(r0 + 8) * HD + c0 + 1] * 0.158113883f : 0.f;
        float q20 = (c1     < HD) ? qb[(size_t)r0 * HD + c1] * 0.158113883f : 0.f;
        float q21 = (c1 + 1 < HD) ? qb[(size_t)r0 * HD + c1 + 1] * 0.158113883f : 0.f;
        float q30 = (c1     < HD) ? qb[(size_t)(r0 + 8) * HD + c1] * 0.158113883f : 0.f;
        float q31 = (c1 + 1 < HD) ? qb[(size_t)(r0 + 8) * HD + c1 + 1] * 0.158113883f : 0.f;
        qa[kt][0] = pack_bf16x2(q00, q01);
        qa[kt][1] = pack_bf16x2(q10, q11);
        qa[kt][2] = pack_bf16x2(q20, q21);
        qa[kt][3] = pack_bf16x2(q30, q31);
    }

    float o[6][4];
    #pragma unroll
    for (int b = 0; b < 6; b++)
        #pragma unroll
        for (int c = 0; c < 4; c++) o[b][c] = 0.f;
    float m[2]  = { -1e30f, -1e30f };
    float mL[2] = { -1e30f, -1e30f };

    const uint32_t sb0 = smem_u32(&buf[0][0]);
    const uint32_t sb1 = smem_u32(&buf[1][0]);
    const char* kg0 = (const char*)kp;
    const char* vg0 = (const char*)vp;

    #pragma unroll
    for (int i = 0; i < 3; i++) {
        int idx = tid + i * 256;
        if (idx < 384) CP_ASYNC16(sb0 + idx * 16, kg0 + (size_t)idx * 16);
        else           CP_ASYNC16(sb0 + idx * 16, vg0 + (size_t)(idx - 384) * 16);
    }
    CP_COMMIT();

    for (int t = 0; t < NTK; t++) {
        CP_WAIT0();
        __syncthreads();

        if (t + 1 < NTK) {
            uint32_t sd = ((t + 1) & 1) ? sb1 : sb0;
            const char* kg = kg0 + (size_t)(t + 1) * KP_TILE * 4;
            const char* vg = vg0 + (size_t)(t + 1) * VP_TILE * 4;
            #pragma unroll
            for (int i = 0; i < 3; i++) {
                int idx = tid + i * 256;
                if (idx < 384) CP_ASYNC16(sd + idx * 16, kg + (size_t)idx * 16);
                else           CP_ASYNC16(sd + idx * 16, vg + (size_t)(idx - 384) * 16);
            }
            CP_COMMIT();
        }

        const uint4* K4 = (const uint4*)((t & 1) ? &buf[1][0] : &buf[0][0]);
        const uint4* V4 = K4 + 384;

        float s[8][4];
        #pragma unroll
        for (int b = 0; b < 8; b++)
            #pragma unroll
            for (int c = 0; c < 4; c++) s[b][c] = 0.f;

        #pragma unroll
        for (int kt = 0; kt < 3; kt++) {
            uint4 f0 = K4[(kt * 4 + 0) * 32 + lane];
            uint4 f1 = K4[(kt * 4 + 1) * 32 + lane];
            uint4 f2 = K4[(kt * 4 + 2) * 32 + lane];
            uint4 f3 = K4[(kt * 4 + 3) * 32 + lane];
            mma_bf16(s[0], qa[kt], f0.x, f0.y);
            mma_bf16(s[1], qa[kt], f0.z, f0.w);
            mma_bf16(s[2], qa[kt], f1.x, f1.y);
            mma_bf16(s[3], qa[kt], f1.z, f1.w);
            mma_bf16(s[4], qa[kt], f2.x, f2.y);
            mma_bf16(s[5], qa[kt], f2.z, f2.w);
            mma_bf16(s[6], qa[kt], f3.x, f3.y);
            mma_bf16(s[7], qa[kt], f3.z, f3.w);
        }

        if (t == NTK - 1) {
            #pragma unroll
            for (int nt = 0; nt < 8; nt++) {
                int base = t * KT + 8 * nt + 2 * tg;
                if (base     >= S1) { s[nt][0] = s[nt][2] = -1e30f; }
                if (base + 1 >= S1) { s[nt][1] = s[nt][3] = -1e30f; }
            }
        }

        float mx[2];
        #pragma unroll
        for (int r = 0; r < 2; r++) {
            float t0 = fmaxf(fmaxf(s[0][2*r], s[0][2*r+1]), fmaxf(s[1][2*r], s[1][2*r+1]));
            float t1 = fmaxf(fmaxf(s[2][2*r], s[2][2*r+1]), fmaxf(s[3][2*r], s[3][2*r+1]));
            float t2 = fmaxf(fmaxf(s[4][2*r], s[4][2*r+1]), fmaxf(s[5][2*r], s[5][2*r+1]));
            float t3 = fmaxf(fmaxf(s[6][2*r], s[6][2*r+1]), fmaxf(s[7][2*r], s[7][2*r+1]));
            float v = fmaxf(fmaxf(t0, t1), fmaxf(t2, t3));
            v = fmaxf(v, __shfl_xor_sync(0xFFFFFFFFu, v, 1));
            v = fmaxf(v, __shfl_xor_sync(0xFFFFFFFFu, v, 2));
            mx[r] = v;
        }
        bool upd = (mx[0] > m[0]) | (mx[1] > m[1]);
        if (__ballot_sync(0xFFFFFFFFu, upd)) {
            float mn0 = fmaxf(m[0], mx[0]);
            float mn1 = fmaxf(m[1], mx[1]);
            float c0 = __expf(m[0] - mn0);
            float c1 = __expf(m[1] - mn1);
            m[0] = mn0; m[1] = mn1;
            mL[0] = mn0 * L2E; mL[1] = mn1 * L2E;
            #pragma unroll
            for (int nt = 0; nt < 6; nt++) {
                o[nt][0] *= c0;
                o[nt][1] *= c0;
                o[nt][2] *= c1;
                o[nt][3] *= c1;
            }
        }

        uint32_t pf[8][2];
        #pragma unroll
        for (int nt = 0; nt < 8; nt++) {
            float f0 = __fmaf_rn(s[nt][0], L2E, -mL[0]);
            float f1 = __fmaf_rn(s[nt][1], L2E, -mL[0]);
            float f2 = __fmaf_rn(s[nt][2], L2E, -mL[1]);
            float f3 = __fmaf_rn(s[nt][3], L2E, -mL[1]);
            pf[nt][0] = pack_ex2_f16x2(f0, f1);
            pf[nt][1] = pack_ex2_f16x2(f2, f3);
        }

        #pragma unroll
        for (int kt = 0; kt < 4; kt++) {
            uint4 b0 = V4[(kt * 3 + 0) * 32 + lane];
            uint4 b1 = V4[(kt * 3 + 1) * 32 + lane];
            uint4 b2 = V4[(kt * 3 + 2) * 32 + lane];
            uint32_t bb[6][2];
            bb[0][0] = b0.x; bb[0][1] = b0.y;
            bb[1][0] = b0.z; bb[1][1] = b0.w;
            bb[2][0] = b1.x; bb[2][1] = b1.y;
            bb[3][0] = b1.z; bb[3][1] = b1.w;
            bb[4][0] = b2.x; bb[4][1] = b2.y;
            bb[5][0] = b2.z; bb[5][1] = b2.w;
            uint32_t aa[4] = { pf[2 * kt][0], pf[2 * kt][1],
                               pf[2 * kt + 1][0], pf[2 * kt + 1][1] };
            #pragma unroll
            for (int nt = 0; nt < 6; nt++) mma_f16(o[nt], aa, bb[nt]);
        }
    }

    {
        float l0 = __shfl_sync(0xFFFFFFFFu, o[5][0], lane & ~3);
        float l1 = __shfl_sync(0xFFFFFFFFu, o[5][2], lane & ~3);
        float inv0 = 1.f / l0, inv1 = 1.f / l1;
        float* ob0 = g_att + ((size_t)bh * S1 + r0) * HD;
        float* ob1 = g_att + ((size_t)bh * S1 + r0 + 8) * HD;
        #pragma unroll
        for (int nt = 0; nt < 5; nt++) {
            int d = 8 * nt + 2 * tg;
            *(float2*)(ob0 + d) = make_float2(o[nt][0] * inv0, o[nt][1] * inv0);
            *(float2*)(ob1 + d) = make_float2(o[nt][2] * inv1, o[nt][3] * inv1);
        }
    }
}

// ================= conv v2 (unchanged) ======================================
#define CONV_SMEM ((16384 + 16384 + 4160 + 10496) * 4)
__global__ void __launch_bounds__(256) k_conv2(const float* __restrict__ x,
                       const float* __restrict__ w1, const float* __restrict__ b1,
                       const float* __restrict__ w2, const float* __restrict__ b2,
                       const float* __restrict__ pe)
{
    extern __shared__ float cs[];
    float* xs  = cs;
    float* w1s = cs + 16384;
    float* o1s = cs + 32768;
    float* w2T = cs + 36928;

    const int i = blockIdx.x, b = blockIdx.y;
    const int tid = threadIdx.x;

    const float4* x4 = (const float4*)x;
    #pragma unroll
    for (int q = 0; q < 16; q++) {
        int idx = tid + q * 256;
        int c0 = idx >> 6, r = idx & 63, ky = r >> 5, w4 = r & 31;
        ((float4*)xs)[c0 * 64 + ky * 32 + w4] =
            x4[(size_t)((b * 64 + c0) * 128 + (2 * i + ky)) * 32 + w4];
    }
    #pragma unroll
    for (int q = 0; q < 16; q++) {
        int idx = tid + q * 256;
        ((float4*)w1s)[idx] = ((const float4*)w1)[idx];
    }
    for (int idx = tid; idx < 10240; idx += 256) {
        int c2 = idx >> 6, c1 = idx & 63;
        w2T[c1 * 164 + c2] = w2[idx];
    }
    __syncthreads();

    {
        const int j0  = (tid & 15) * 4;
        const int c10 = (tid >> 4) * 4;
        float a1[4][4] = {};
        #pragma unroll 4
        for (int c0 = 0; c0 < 64; c0++) {
            float4 wv[4];
            #pragma unroll
            for (int cc = 0; cc < 4; cc++)
                wv[cc] = *(float4*)&w1s[(c10 + cc) * 256 + c0 * 4];
            #pragma unroll
            for (int jj = 0; jj < 4; jj++) {
                float2 x0 = *(float2*)&xs[c0 * 256 + 2 * (j0 + jj)];
                float2 x1 = *(float2*)&xs[c0 * 256 + 128 + 2 * (j0 + jj)];
                #pragma unroll
                for (int cc = 0; cc < 4; cc++)
                    a1[jj][cc] += x0.x * wv[cc].x + x0.y * wv[cc].y
                                + x1.x * wv[cc].z + x1.y * wv[cc].w;
            }
        }
        #pragma unroll
        for (int jj = 0; jj < 4; jj++)
            #pragma unroll
            for (int cc = 0; cc < 4; cc++)
                o1s[(j0 + jj) * 65 + c10 + cc] = b1[c10 + cc] + a1[jj][cc];
    }
    __syncthreads();

    {
        const int jj2 = tid & 31;
        const int c20 = (tid >> 5) * 20;
        float a2[2][20] = {};
        #pragma unroll 4
        for (int c1 = 0; c1 < 64; c1++) {
            float p0 = o1s[(2 * jj2) * 65 + c1];
            float p1 = o1s[(2 * jj2 + 1) * 65 + c1];
            #pragma unroll
            for (int q = 0; q < 5; q++) {
                float4 wv = *(float4*)&w2T[c1 * 164 + c20 + q * 4];
                a2[0][q * 4 + 0] += p0 * wv.x; a2[1][q * 4 + 0] += p1 * wv.x;
                a2[0][q * 4 + 1] += p0 * wv.y; a2[1][q * 4 + 1] += p1 * wv.y;
                a2[0][q * 4 + 2] += p0 * wv.z; a2[1][q * 4 + 2] += p1 * wv.z;
                a2[0][q * 4 + 3] += p0 * wv.w; a2[1][q * 4 + 3] += p1 * wv.w;
            }
        }
        #pragma unroll
        for (int row = 0; row < 2; row++) {
            int j = 2 * jj2 + row;
            int s = i * 64 + j;
            float pev = pe[s];
            #pragma unroll
            for (int cc = 0; cc < 20; cc++) {
                int c2 = c20 + cc;
                float v = a2[row][cc] + b2[c2];
                v = (v >= 0.f) ? v : 0.01f * v;
                g_f[((size_t)b * S1 + s) * DM + c2] = v + pev;
            }
        }
    }
}

__global__ void k_pad(const float* __restrict__ pe)
{
    int t = blockIdx.x * blockDim.x + threadIdx.x;
    if (t < BATCH * DM) {
        int b = t / DM, c = t % DM;
        g_f[((size_t)b * S1 + SMAX) * DM + c] = pe[SMAX];
    }
}

// ================= LN stats (unchanged) =====================================
__global__ void __launch_bounds__(256) k_stats2()
{
    int gw = blockIdx.x * 8 + (threadIdx.x >> 5);
    int lane = threadIdx.x & 31;
    int b = gw >> 12, s = gw & 4095;

    float sum = 0.f, sq = 0.f;
    #pragma unroll
    for (int j = 0; j < 5; j++) {
        int c = lane + 32 * j;
        int h = c / HD, d = c % HD;
        float v = g_att[(((size_t)b * NH + h) * S1 + s) * HD + d];
        sum += v; sq += v * v;
    }
    #pragma unroll
    for (int off = 16; off > 0; off >>= 1) {
        sum += __shfl_xor_sync(0xFFFFFFFFu, sum, off);
        sq  += __shfl_xor_sync(0xFFFFFFFFu, sq, off);
    }
    if (lane == 0) {
        float mean = sum * (1.f / DM);
        float var  = sq * (1.f / DM) - mean * mean;
        g_stats[2 * gw]     = mean;
        g_stats[2 * gw + 1] = rsqrtf(var + 1e-5f);
    }
}

// ================= LN + residual + upsample v2: smem-staged reads ===========
__global__ void __launch_bounds__(256) k_out2(const float* __restrict__ ln_w,
                                              const float* __restrict__ ln_b,
                                              float* __restrict__ out)
{
    __shared__ float att_s[32 * 9];      // [j][c-sub], stride 9 (conflict-free)
    __shared__ float st_s[64];           // mean/rstd for 32 s values

    const int tid = threadIdx.x;         // 256
    const int bx = blockIdx.x, i = blockIdx.y, bz = blockIdx.z;
    const int b = bz / 20, cg = bz % 20;
    const int j0 = bx * 32;
    const int s0 = i * 64 + j0;
    const int c0 = cg * 8;
    const int h = c0 / HD, d0 = c0 % HD;  // 8-block never crosses a head (8 | 40)

    // stage: 32 s-rows x 8 channels, sector-efficient (8 contiguous floats/row)
    {
        int sl = tid >> 3, dd = tid & 7;
        att_s[sl * 9 + dd] =
            g_att[(((size_t)b * NH + h) * S1 + (s0 + sl)) * HD + (d0 + dd)];
    }
    if (tid < 64) st_s[tid] = g_stats[2 * (b * SMAX + s0) + tid];
    __syncthreads();

    const int tx = tid & 31;             // j within tile
    const int ty = tid >> 5;             // c-sub 0..7
    const int c = c0 + ty;
    const int j = j0 + tx;

    float v    = att_s[tx * 9 + ty];
    float mean = st_s[2 * tx];
    float rstd = st_s[2 * tx + 1];
    float ln = (v - mean) * rstd * ln_w[c] + ln_b[c];
    float ov = ln + v;

    size_t base = (((size_t)b * DM + c) * 128 + 2 * i) * 128 + 2 * j;
    float2 v2 = make_float2(ov, ov);
    *(float2*)(out + base)       = v2;
    *(float2*)(out + base + 128) = v2;
}

// ---------------- launch ----------------
extern "C" void kernel_launch(void* const* d_in, const int* in_sizes, int n_in,
                              void* d_out, int out_size)
{
    const float* x   = (const float*)d_in[0];
    const float* w1  = (const float*)d_in[1];
    const float* b1  = (const float*)d_in[2];
    const float* w2  = (const float*)d_in[3];
    const float* b2  = (const float*)d_in[4];
    const float* pe  = (const float*)d_in[5];
    const float* wq  = (const float*)d_in[6];
    const float* wk  = (const float*)d_in[7];
    const float* wv  = (const float*)d_in[8];
    const float* lnw = (const float*)d_in[9];
    const float* lnb = (const float*)d_in[10];
    float* out = (float*)d_out;

    static int attr_set = 0;
    if (!attr_set) {
        cudaFuncSetAttribute(k_conv2, cudaFuncAttributeMaxDynamicSharedMemorySize, CONV_SMEM);
        attr_set = 1;
    }

    k_wprep<<<3, 256>>>(wq, wk, wv);
    k_conv2<<<dim3(64, BATCH), 256, CONV_SMEM>>>(x, w1, b1, w2, b2, pe);
    k_pad<<<1, BATCH * DM>>>(pe);
    k_qkv4<<<dim3((NROWS + 127) / 128, 3), 256>>>();
    k_prep<<<dim3(NTK, BATCH * NH), 128>>>();
    k_flash5<<<dim3(SMAX / 128, BATCH * NH), 256>>>();
    k_stats2<<<BATCH * SMAX / 8, 256>>>();
    k_out2<<<dim3(2, 64, BATCH * 20), 256>>>(lnw, lnb, out);
}

// round 16
// speedup vs baseline: 1.0430x; 1.0430x over previous
#include <cuda_runtime.h>
#include <cuda_fp16.h>
#include <cuda_bf16.h>
#include <cstdint>

#define S1 4097
#define SMAX 4096
#define DM 160
#define NH 4
#define HD 40
#define BATCH 4
#define KT 64
#define NTK 65           // ceil(4097/64)
#define NROWS (BATCH * S1)
#define L2E 1.4426950408889634f
#define KP_TILE 1536     // u32 per K fragment tile (3kt*4j*32lane*4) bf16x2
#define VP_TILE 1536     // u32 per V fragment tile (4kt*3j*32lane*4) f16x2

// ---------------- device scratch ----------------
__device__ float g_f[BATCH * S1 * DM];
__device__ float g_q[BATCH * NH * S1 * HD];
__device__ float g_k[BATCH * NH * S1 * HD];
__device__ float g_v[BATCH * NH * S1 * HD];
__device__ float g_att[BATCH * NH * S1 * HD];
__device__ float g_stats[BATCH * SMAX * 2];
__device__ uint32_t g_kp[BATCH * NH * NTK * KP_TILE];   // K in bf16 B-frag order
__device__ uint32_t g_vp[BATCH * NH * NTK * VP_TILE];   // V in f16 B-frag order
__device__ uint4    g_wp[3 * 6400];                     // qkv weights, tf32 B-frag order

// ---------------- helpers ----------------
__device__ __forceinline__ void mma_bf16(float* c, const uint32_t* a, uint32_t b0, uint32_t b1) {
    asm volatile(
        "mma.sync.aligned.m16n8k16.row.col.f32.bf16.bf16.f32 "
        "{%0,%1,%2,%3}, {%4,%5,%6,%7}, {%8,%9}, {%0,%1,%2,%3};"
        : "+f"(c[0]), "+f"(c[1]), "+f"(c[2]), "+f"(c[3])
        : "r"(a[0]), "r"(a[1]), "r"(a[2]), "r"(a[3]), "r"(b0), "r"(b1));
}
__device__ __forceinline__ void mma_tf32(float* c, const uint32_t* a, uint32_t b0, uint32_t b1) {
    asm volatile(
        "mma.sync.aligned.m16n8k8.row.col.f32.tf32.tf32.f32 "
        "{%0,%1,%2,%3}, {%4,%5,%6,%7}, {%8,%9}, {%0,%1,%2,%3};"
        : "+f"(c[0]), "+f"(c[1]), "+f"(c[2]), "+f"(c[3])
        : "r"(a[0]), "r"(a[1]), "r"(a[2]), "r"(a[3]), "r"(b0), "r"(b1));
}
__device__ __forceinline__ void mma_f16(float* c, const uint32_t* a, uint32_t b0, uint32_t b1) {
    asm volatile(
        "mma.sync.aligned.m16n8k16.row.col.f32.f16.f16.f32 "
        "{%0,%1,%2,%3}, {%4,%5,%6,%7}, {%8,%9}, {%0,%1,%2,%3};"
        : "+f"(c[0]), "+f"(c[1]), "+f"(c[2]), "+f"(c[3])
        : "r"(a[0]), "r"(a[1]), "r"(a[2]), "r"(a[3]), "r"(b0), "r"(b1));
}
__device__ __forceinline__ float to_tf32(float x) {
    float r;
    asm("cvt.rna.tf32.f32 %0, %1;" : "=f"(r) : "f"(x));
    return r;
}
__device__ __forceinline__ uint32_t pack_bf16x2(float lo, float hi) {
    uint32_t p;
    asm("cvt.rn.bf16x2.f32 %0, %1, %2;" : "=r"(p) : "f"(hi), "f"(lo));
    return p;
}
__device__ __forceinline__ uint32_t pack_ex2_f16x2(float lo, float hi) {
    uint32_t p, r;
    asm("cvt.rn.f16x2.f32 %0, %1, %2;" : "=r"(p) : "f"(hi), "f"(lo));
    asm("ex2.approx.f16x2 %0, %1;" : "=r"(r) : "r"(p));
    return r;
}
__device__ __forceinline__ uint32_t pack_f16x2(float lo, float hi) {
    uint32_t p;
    asm("cvt.rn.f16x2.f32 %0, %1, %2;" : "=r"(p) : "f"(hi), "f"(lo));
    return p;
}
__device__ __forceinline__ uint32_t smem_u32(const void* p) {
    uint32_t a;
    asm("{ .reg .u64 t; cvta.to.shared.u64 t, %1; cvt.u32.u64 %0, t; }" : "=r"(a) : "l"(p));
    return a;
}
#define CP_ASYNC16(sdst, gsrc) \
    asm volatile("cp.async.cg.shared.global [%0], [%1], 16;" :: "r"(sdst), "l"(gsrc))
#define CP_COMMIT() asm volatile("cp.async.commit_group;")
#define CP_WAIT0()  asm volatile("cp.async.wait_group 0;")

// ================= wprep: qkv weights -> tf32 B-fragment order ==============
__global__ void __launch_bounds__(256) k_wprep(const float* __restrict__ wq,
                                               const float* __restrict__ wk,
                                               const float* __restrict__ wv)
{
    int mat = blockIdx.x;
    const float* w = (mat == 0) ? wq : ((mat == 1) ? wk : wv);
    for (int idx = threadIdx.x; idx < 6400; idx += 256) {
        int lane = idx & 31, rest = idx >> 5;
        int ntp = rest % 10, kt = rest / 10;
        int g = lane >> 2, tg = lane & 3;
        uint4 val;
        uint32_t* vv = (uint32_t*)&val;
        #pragma unroll
        for (int e = 0; e < 4; e++) {
            int nt = 2 * ntp + (e >> 1), reg = e & 1;
            int n = g + 8 * nt;
            int kcol = 8 * kt + tg + 4 * reg;
            vv[e] = __float_as_uint(to_tf32(w[n * DM + kcol]));
        }
        g_wp[mat * 6400 + idx] = val;
    }
}

// ================= QKV v4 (round-13 form: best measured, 38us) ==============
__global__ void __launch_bounds__(256) k_qkv4()
{
    __shared__ uint4 wbuf[2][320];

    const int tid = threadIdx.x, w = tid >> 5, lane = tid & 31;
    const int g = lane >> 2, tg = lane & 3;
    const int row0 = blockIdx.x * 128;
    const int mat = blockIdx.y;
    const uint4* wp = g_wp + mat * 6400;
    float* outp = (mat == 0) ? g_q : ((mat == 1) ? g_k : g_v);

    const int rA = row0 + w * 16 + g;
    const int rB = rA + 8;
    const bool vA = rA < NROWS, vB = rB < NROWS;
    const float* fA = g_f + (size_t)rA * DM;
    const float* fB = g_f + (size_t)rB * DM;

    uint32_t a[20][4];
    #pragma unroll
    for (int kt = 0; kt < 20; kt++) {
        int c0 = 8 * kt + tg, c1 = c0 + 4;
        a[kt][0] = vA ? __float_as_uint(to_tf32(fA[c0])) : 0u;
        a[kt][1] = vB ? __float_as_uint(to_tf32(fB[c0])) : 0u;
        a[kt][2] = vA ? __float_as_uint(to_tf32(fA[c1])) : 0u;
        a[kt][3] = vB ? __float_as_uint(to_tf32(fB[c1])) : 0u;
    }

    float acc[20][4];
    #pragma unroll
    for (int nt = 0; nt < 20; nt++)
        #pragma unroll
        for (int c = 0; c < 4; c++) acc[nt][c] = 0.f;

    const uint32_t sw0 = smem_u32(&wbuf[0][0]);
    const uint32_t sw1 = smem_u32(&wbuf[1][0]);

    {
        const char* wg = (const char*)wp;
        CP_ASYNC16(sw0 + tid * 16, wg + (size_t)tid * 16);
        if (tid < 64) CP_ASYNC16(sw0 + (tid + 256) * 16, wg + (size_t)(tid + 256) * 16);
        CP_COMMIT();
    }

    for (int kt = 0; kt < 20; kt++) {
        CP_WAIT0();
        __syncthreads();
        if (kt + 1 < 20) {
            uint32_t sd = ((kt + 1) & 1) ? sw1 : sw0;
            const char* wg = (const char*)(wp + (kt + 1) * 320);
            CP_ASYNC16(sd + tid * 16, wg + (size_t)tid * 16);
            if (tid < 64) CP_ASYNC16(sd + (tid + 256) * 16, wg + (size_t)(tid + 256) * 16);
            CP_COMMIT();
        }
        const uint4* wb = (kt & 1) ? &wbuf[1][0] : &wbuf[0][0];
        #pragma unroll
        for (int ntp = 0; ntp < 10; ntp++) {
            uint4 b = wb[ntp * 32 + lane];
            mma_tf32(acc[2 * ntp],     a[kt], b.x, b.y);
            mma_tf32(acc[2 * ntp + 1], a[kt], b.z, b.w);
        }
        __syncthreads();
    }

    #pragma unroll
    for (int nt = 0; nt < 20; nt++) {
        int n0 = 8 * nt + 2 * tg;
        int h = n0 / HD, d = n0 % HD;
        if (vA) {
            int b = rA / S1, s = rA % S1;
            *(float2*)&outp[(((size_t)b * NH + h) * S1 + s) * HD + d] =
                make_float2(acc[nt][0], acc[nt][1]);
        }
        if (vB) {
            int b = rB / S1, s = rB % S1;
            *(float2*)&outp[(((size_t)b * NH + h) * S1 + s) * HD + d] =
                make_float2(acc[nt][2], acc[nt][3]);
        }
    }
}

// ================= prep: K(bf16)/V(f16) -> fragment-order scratch ===========
__global__ void __launch_bounds__(128) k_prep()
{
    int t = blockIdx.x, bh = blockIdx.y;
    int tid = threadIdx.x, lane = tid & 31, w = tid >> 5;
    int g = lane >> 2, tg = lane & 3;
    const float* kb = g_k + (size_t)bh * S1 * HD;
    const float* vb = g_v + (size_t)bh * S1 * HD;
    uint32_t* kp = g_kp + ((size_t)bh * NTK + t) * KP_TILE;
    uint32_t* vp = g_vp + ((size_t)bh * NTK + t) * VP_TILE;

    for (int c = w; c < 24; c += 4) {
        if (c < 12) {
            int kt = c >> 2, j = c & 3;
            uint4 val;
            uint32_t* vv = (uint32_t*)&val;
            #pragma unroll
            for (int e = 0; e < 4; e++) {
                int idx = j * 4 + e, nt = idx >> 1, reg = idx & 1;
                int key = t * KT + g + 8 * nt;
                int col = 16 * kt + 2 * (tg + 4 * reg);
                float v0 = (key < S1 && col     < HD) ? kb[(size_t)key * HD + col]     : 0.f;
                float v1 = (key < S1 && col + 1 < HD) ? kb[(size_t)key * HD + col + 1] : 0.f;
                vv[e] = pack_bf16x2(v0, v1);
            }
            ((uint4*)kp)[(kt * 4 + j) * 32 + lane] = val;
        } else {
            int cc = c - 12, kt = cc / 3, j = cc % 3;
            uint4 val;
            uint32_t* vv = (uint32_t*)&val;
            #pragma unroll
            for (int e = 0; e < 4; e++) {
                int idx = j * 4 + e, nt = idx >> 1, reg = idx & 1;
                int p = 8 * kt + tg + 4 * reg;
                int d = g + 8 * nt;
                uint32_t r;
                if (d == 40) r = 0x3C003C00u;
                else if (d > 40) r = 0u;
                else {
                    int k0 = t * KT + 2 * p;
                    float v0 = (k0     < S1) ? vb[(size_t)k0 * HD + d]       : 0.f;
                    float v1 = (k0 + 1 < S1) ? vb[(size_t)(k0 + 1) * HD + d] : 0.f;
                    r = pack_f16x2(v0, v1);
                }
                vv[e] = r;
            }
            ((uint4*)vp)[(kt * 3 + j) * 32 + lane] = val;
        }
    }
}

// ================= flash attention v6: 4 warps x 2 mtiles, halved B-LDS =====
__global__ void __launch_bounds__(128) k_flash6()
{
    __shared__ uint4 buf[2][768];

    const int tid = threadIdx.x, w = tid >> 5, lane = tid & 31;
    const int g = lane >> 2, tg = lane & 3;
    const int qt = blockIdx.x, bh = blockIdx.y;

    const float*    qb = g_q  + (size_t)bh * S1 * HD;
    const uint32_t* kp = g_kp + (size_t)bh * NTK * KP_TILE;
    const uint32_t* vp = g_vp + (size_t)bh * NTK * VP_TILE;

    // warp w owns rows [qt*128 + w*32, +32): mtiles at +0 and +16
    const int r0 = qt * 128 + w * 32 + g;
    uint32_t qa[2][3][4];
    #pragma unroll
    for (int mt = 0; mt < 2; mt++) {
        int rr = r0 + 16 * mt;
        #pragma unroll
        for (int kt = 0; kt < 3; kt++) {
            int c0 = 16 * kt + 2 * tg;
            int c1 = c0 + 8;
            float q00 = (c0     < HD) ? qb[(size_t)rr * HD + c0] * 0.158113883f : 0.f;
            float q01 = (c0 + 1 < HD) ? qb[(size_t)rr * HD + c0 + 1] * 0.158113883f : 0.f;
            float q10 = (c0     < HD) ? qb[(size_t)(rr + 8) * HD + c0] * 0.158113883f : 0.f;
            float q11 = (c0 + 1 < HD) ? qb[(size_t)(rr + 8) * HD + c0 + 1] * 0.158113883f : 0.f;
            float q20 = (c1     < HD) ? qb[(size_t)rr * HD + c1] * 0.158113883f : 0.f;
            float q21 = (c1 + 1 < HD) ? qb[(size_t)rr * HD + c1 + 1] * 0.158113883f : 0.f;
            float q30 = (c1     < HD) ? qb[(size_t)(rr + 8) * HD + c1] * 0.158113883f : 0.f;
            float q31 = (c1 + 1 < HD) ? qb[(size_t)(rr + 8) * HD + c1 + 1] * 0.158113883f : 0.f;
            qa[mt][kt][0] = pack_bf16x2(q00, q01);
            qa[mt][kt][1] = pack_bf16x2(q10, q11);
            qa[mt][kt][2] = pack_bf16x2(q20, q21);
            qa[mt][kt][3] = pack_bf16x2(q30, q31);
        }
    }

    float o[2][6][4];
    #pragma unroll
    for (int mt = 0; mt < 2; mt++)
        #pragma unroll
        for (int b = 0; b < 6; b++)
            #pragma unroll
            for (int c = 0; c < 4; c++) o[mt][b][c] = 0.f;
    float m[4]  = { -1e30f, -1e30f, -1e30f, -1e30f };
    float mL[4] = { -1e30f, -1e30f, -1e30f, -1e30f };

    const uint32_t sb0 = smem_u32(&buf[0][0]);
    const uint32_t sb1 = smem_u32(&buf[1][0]);
    const char* kg0 = (const char*)kp;
    const char* vg0 = (const char*)vp;

    // prefetch tile 0 (768 uint4 / 128 threads = 6 each)
    #pragma unroll
    for (int i = 0; i < 6; i++) {
        int idx = tid + i * 128;
        if (idx < 384) CP_ASYNC16(sb0 + idx * 16, kg0 + (size_t)idx * 16);
        else           CP_ASYNC16(sb0 + idx * 16, vg0 + (size_t)(idx - 384) * 16);
    }
    CP_COMMIT();

    for (int t = 0; t < NTK; t++) {
        CP_WAIT0();
        __syncthreads();

        if (t + 1 < NTK) {
            uint32_t sd = ((t + 1) & 1) ? sb1 : sb0;
            const char* kg = kg0 + (size_t)(t + 1) * KP_TILE * 4;
            const char* vg = vg0 + (size_t)(t + 1) * VP_TILE * 4;
            #pragma unroll
            for (int i = 0; i < 6; i++) {
                int idx = tid + i * 128;
                if (idx < 384) CP_ASYNC16(sd + idx * 16, kg + (size_t)idx * 16);
                else           CP_ASYNC16(sd + idx * 16, vg + (size_t)(idx - 384) * 16);
            }
            CP_COMMIT();
        }

        const uint4* K4 = (const uint4*)((t & 1) ? &buf[1][0] : &buf[0][0]);
        const uint4* V4 = K4 + 384;

        // ---- S = Q K^T (one B-load serves both mtiles) ----
        float s[2][8][4];
        #pragma unroll
        for (int mt = 0; mt < 2; mt++)
            #pragma unroll
            for (int b = 0; b < 8; b++)
                #pragma unroll
                for (int c = 0; c < 4; c++) s[mt][b][c] = 0.f;

        #pragma unroll
        for (int kt = 0; kt < 3; kt++) {
            uint4 f0 = K4[(kt * 4 + 0) * 32 + lane];
            uint4 f1 = K4[(kt * 4 + 1) * 32 + lane];
            uint4 f2 = K4[(kt * 4 + 2) * 32 + lane];
            uint4 f3 = K4[(kt * 4 + 3) * 32 + lane];
            #pragma unroll
            for (int mt = 0; mt < 2; mt++) {
                mma_bf16(s[mt][0], qa[mt][kt], f0.x, f0.y);
                mma_bf16(s[mt][1], qa[mt][kt], f0.z, f0.w);
                mma_bf16(s[mt][2], qa[mt][kt], f1.x, f1.y);
                mma_bf16(s[mt][3], qa[mt][kt], f1.z, f1.w);
                mma_bf16(s[mt][4], qa[mt][kt], f2.x, f2.y);
                mma_bf16(s[mt][5], qa[mt][kt], f2.z, f2.w);
                mma_bf16(s[mt][6], qa[mt][kt], f3.x, f3.y);
                mma_bf16(s[mt][7], qa[mt][kt], f3.z, f3.w);
            }
        }

        if (t == NTK - 1) {
            #pragma unroll
            for (int nt = 0; nt < 8; nt++) {
                int base = t * KT + 8 * nt + 2 * tg;
                if (base >= S1) {
                    s[0][nt][0] = s[0][nt][2] = s[1][nt][0] = s[1][nt][2] = -1e30f;
                }
                if (base + 1 >= S1) {
                    s[0][nt][1] = s[0][nt][3] = s[1][nt][1] = s[1][nt][3] = -1e30f;
                }
            }
        }

        // ---- tree row max (4 row-halves) + ballot-gated rescale ----
        float mx[4];
        #pragma unroll
        for (int r = 0; r < 4; r++) {
            int mt = r >> 1, hf = r & 1;
            float t0 = fmaxf(fmaxf(s[mt][0][2*hf], s[mt][0][2*hf+1]),
                             fmaxf(s[mt][1][2*hf], s[mt][1][2*hf+1]));
            float t1 = fmaxf(fmaxf(s[mt][2][2*hf], s[mt][2][2*hf+1]),
                             fmaxf(s[mt][3][2*hf], s[mt][3][2*hf+1]));
            float t2 = fmaxf(fmaxf(s[mt][4][2*hf], s[mt][4][2*hf+1]),
                             fmaxf(s[mt][5][2*hf], s[mt][5][2*hf+1]));
            float t3 = fmaxf(fmaxf(s[mt][6][2*hf], s[mt][6][2*hf+1]),
                             fmaxf(s[mt][7][2*hf], s[mt][7][2*hf+1]));
            float v = fmaxf(fmaxf(t0, t1), fmaxf(t2, t3));
            v = fmaxf(v, __shfl_xor_sync(0xFFFFFFFFu, v, 1));
            v = fmaxf(v, __shfl_xor_sync(0xFFFFFFFFu, v, 2));
            mx[r] = v;
        }
        bool upd = (mx[0] > m[0]) | (mx[1] > m[1]) | (mx[2] > m[2]) | (mx[3] > m[3]);
        if (__ballot_sync(0xFFFFFFFFu, upd)) {
            float cr[4];
            #pragma unroll
            for (int r = 0; r < 4; r++) {
                float mn = fmaxf(m[r], mx[r]);
                cr[r] = __expf(m[r] - mn);
                m[r] = mn;
                mL[r] = mn * L2E;
            }
            #pragma unroll
            for (int mt = 0; mt < 2; mt++)
                #pragma unroll
                for (int nt = 0; nt < 6; nt++) {
                    o[mt][nt][0] *= cr[2 * mt];
                    o[mt][nt][1] *= cr[2 * mt];
                    o[mt][nt][2] *= cr[2 * mt + 1];
                    o[mt][nt][3] *= cr[2 * mt + 1];
                }
        }

        uint32_t pf[2][8][2];
        #pragma unroll
        for (int mt = 0; mt < 2; mt++)
            #pragma unroll
            for (int nt = 0; nt < 8; nt++) {
                float f0 = __fmaf_rn(s[mt][nt][0], L2E, -mL[2 * mt]);
                float f1 = __fmaf_rn(s[mt][nt][1], L2E, -mL[2 * mt]);
                float f2 = __fmaf_rn(s[mt][nt][2], L2E, -mL[2 * mt + 1]);
                float f3 = __fmaf_rn(s[mt][nt][3], L2E, -mL[2 * mt + 1]);
                pf[mt][nt][0] = pack_ex2_f16x2(f0, f1);
                pf[mt][nt][1] = pack_ex2_f16x2(f2, f3);
            }

        // ---- O += P V (one B-load serves both mtiles) ----
        #pragma unroll
        for (int kt = 0; kt < 4; kt++) {
            uint4 b0 = V4[(kt * 3 + 0) * 32 + lane];
            uint4 b1 = V4[(kt * 3 + 1) * 32 + lane];
            uint4 b2 = V4[(kt * 3 + 2) * 32 + lane];
            #pragma unroll
            for (int mt = 0; mt < 2; mt++) {
                uint32_t aa[4] = { pf[mt][2 * kt][0], pf[mt][2 * kt][1],
                                   pf[mt][2 * kt + 1][0], pf[mt][2 * kt + 1][1] };
                mma_f16(o[mt][0], aa, b0.x, b0.y);
                mma_f16(o[mt][1], aa, b0.z, b0.w);
                mma_f16(o[mt][2], aa, b1.x, b1.y);
                mma_f16(o[mt][3], aa, b1.z, b1.w);
                mma_f16(o[mt][4], aa, b2.x, b2.y);
                mma_f16(o[mt][5], aa, b2.z, b2.w);
            }
        }
    }

    // ---- epilogue ----
    #pragma unroll
    for (int mt = 0; mt < 2; mt++) {
        float l0 = __shfl_sync(0xFFFFFFFFu, o[mt][5][0], lane & ~3);
        float l1 = __shfl_sync(0xFFFFFFFFu, o[mt][5][2], lane & ~3);
        float inv0 = 1.f / l0, inv1 = 1.f / l1;
        int rr = r0 + 16 * mt;
        float* ob0 = g_att + ((size_t)bh * S1 + rr) * HD;
        float* ob1 = g_att + ((size_t)bh * S1 + rr + 8) * HD;
        #pragma unroll
        for (int nt = 0; nt < 5; nt++) {
            int d = 8 * nt + 2 * tg;
            *(float2*)(ob0 + d) = make_float2(o[mt][nt][0] * inv0, o[mt][nt][1] * inv0);
            *(float2*)(ob1 + d) = make_float2(o[mt][nt][2] * inv1, o[mt][nt][3] * inv1);
        }
    }
}

// ================= conv v2 (unchanged) ======================================
#define CONV_SMEM ((16384 + 16384 + 4160 + 10496) * 4)
__global__ void __launch_bounds__(256) k_conv2(const float* __restrict__ x,
                       const float* __restrict__ w1, const float* __restrict__ b1,
                       const float* __restrict__ w2, const float* __restrict__ b2,
                       const float* __restrict__ pe)
{
    extern __shared__ float cs[];
    float* xs  = cs;
    float* w1s = cs + 16384;
    float* o1s = cs + 32768;
    float* w2T = cs + 36928;

    const int i = blockIdx.x, b = blockIdx.y;
    const int tid = threadIdx.x;

    const float4* x4 = (const float4*)x;
    #pragma unroll
    for (int q = 0; q < 16; q++) {
        int idx = tid + q * 256;
        int c0 = idx >> 6, r = idx & 63, ky = r >> 5, w4 = r & 31;
        ((float4*)xs)[c0 * 64 + ky * 32 + w4] =
            x4[(size_t)((b * 64 + c0) * 128 + (2 * i + ky)) * 32 + w4];
    }
    #pragma unroll
    for (int q = 0; q < 16; q++) {
        int idx = tid + q * 256;
        ((float4*)w1s)[idx] = ((const float4*)w1)[idx];
    }
    for (int idx = tid; idx < 10240; idx += 256) {
        int c2 = idx >> 6, c1 = idx & 63;
        w2T[c1 * 164 + c2] = w2[idx];
    }
    __syncthreads();

    {
        const int j0  = (tid & 15) * 4;
        const int c10 = (tid >> 4) * 4;
        float a1[4][4] = {};
        #pragma unroll 4
        for (int c0 = 0; c0 < 64; c0++) {
            float4 wv[4];
            #pragma unroll
            for (int cc = 0; cc < 4; cc++)
                wv[cc] = *(float4*)&w1s[(c10 + cc) * 256 + c0 * 4];
            #pragma unroll
            for (int jj = 0; jj < 4; jj++) {
                float2 x0 = *(float2*)&xs[c0 * 256 + 2 * (j0 + jj)];
                float2 x1 = *(float2*)&xs[c0 * 256 + 128 + 2 * (j0 + jj)];
                #pragma unroll
                for (int cc = 0; cc < 4; cc++)
                    a1[jj][cc] += x0.x * wv[cc].x + x0.y * wv[cc].y
                                + x1.x * wv[cc].z + x1.y * wv[cc].w;
            }
        }
        #pragma unroll
        for (int jj = 0; jj < 4; jj++)
            #pragma unroll
            for (int cc = 0; cc < 4; cc++)
                o1s[(j0 + jj) * 65 + c10 + cc] = b1[c10 + cc] + a1[jj][cc];
    }
    __syncthreads();

    {
        const int jj2 = tid & 31;
        const int c20 = (tid >> 5) * 20;
        float a2[2][20] = {};
        #pragma unroll 4
        for (int c1 = 0; c1 < 64; c1++) {
            float p0 = o1s[(2 * jj2) * 65 + c1];
            float p1 = o1s[(2 * jj2 + 1) * 65 + c1];
            #pragma unroll
            for (int q = 0; q < 5; q++) {
                float4 wv = *(float4*)&w2T[c1 * 164 + c20 + q * 4];
                a2[0][q * 4 + 0] += p0 * wv.x; a2[1][q * 4 + 0] += p1 * wv.x;
                a2[0][q * 4 + 1] += p0 * wv.y; a2[1][q * 4 + 1] += p1 * wv.y;
                a2[0][q * 4 + 2] += p0 * wv.z; a2[1][q * 4 + 2] += p1 * wv.z;
                a2[0][q * 4 + 3] += p0 * wv.w; a2[1][q * 4 + 3] += p1 * wv.w;
            }
        }
        #pragma unroll
        for (int row = 0; row < 2; row++) {
            int j = 2 * jj2 + row;
            int s = i * 64 + j;
            float pev = pe[s];
            #pragma unroll
            for (int cc = 0; cc < 20; cc++) {
                int c2 = c20 + cc;
                float v = a2[row][cc] + b2[c2];
                v = (v >= 0.f) ? v : 0.01f * v;
                g_f[((size_t)b * S1 + s) * DM + c2] = v + pev;
            }
        }
    }
}

__global__ void k_pad(const float* __restrict__ pe)
{
    int t = blockIdx.x * blockDim.x + threadIdx.x;
    if (t < BATCH * DM) {
        int b = t / DM, c = t % DM;
        g_f[((size_t)b * S1 + SMAX) * DM + c] = pe[SMAX];
    }
}

// ================= LN stats (unchanged) =====================================
__global__ void __launch_bounds__(256) k_stats2()
{
    int gw = blockIdx.x * 8 + (threadIdx.x >> 5);
    int lane = threadIdx.x & 31;
    int b = gw >> 12, s = gw & 4095;

    float sum = 0.f, sq = 0.f;
    #pragma unroll
    for (int j = 0; j < 5; j++) {
        int c = lane + 32 * j;
        int h = c / HD, d = c % HD;
        float v = g_att[(((size_t)b * NH + h) * S1 + s) * HD + d];
        sum += v; sq += v * v;
    }
    #pragma unroll
    for (int off = 16; off > 0; off >>= 1) {
        sum += __shfl_xor_sync(0xFFFFFFFFu, sum, off);
        sq  += __shfl_xor_sync(0xFFFFFFFFu, sq, off);
    }
    if (lane == 0) {
        float mean = sum * (1.f / DM);
        float var  = sq * (1.f / DM) - mean * mean;
        g_stats[2 * gw]     = mean;
        g_stats[2 * gw + 1] = rsqrtf(var + 1e-5f);
    }
}

// ================= LN + residual + upsample v2 (unchanged) ==================
__global__ void __launch_bounds__(256) k_out2(const float* __restrict__ ln_w,
                                              const float* __restrict__ ln_b,
                                              float* __restrict__ out)
{
    __shared__ float att_s[32 * 9];
    __shared__ float st_s[64];

    const int tid = threadIdx.x;
    const int bx = blockIdx.x, i = blockIdx.y, bz = blockIdx.z;
    const int b = bz / 20, cg = bz % 20;
    const int j0 = bx * 32;
    const int s0 = i * 64 + j0;
    const int c0 = cg * 8;
    const int h = c0 / HD, d0 = c0 % HD;

    {
        int sl = tid >> 3, dd = tid & 7;
        att_s[sl * 9 + dd] =
            g_att[(((size_t)b * NH + h) * S1 + (s0 + sl)) * HD + (d0 + dd)];
    }
    if (tid < 64) st_s[tid] = g_stats[2 * (b * SMAX + s0) + tid];
    __syncthreads();

    const int tx = tid & 31;
    const int ty = tid >> 5;
    const int c = c0 + ty;
    const int j = j0 + tx;

    float v    = att_s[tx * 9 + ty];
    float mean = st_s[2 * tx];
    float rstd = st_s[2 * tx + 1];
    float ln = (v - mean) * rstd * ln_w[c] + ln_b[c];
    float ov = ln + v;

    size_t base = (((size_t)b * DM + c) * 128 + 2 * i) * 128 + 2 * j;
    float2 v2 = make_float2(ov, ov);
    *(float2*)(out + base)       = v2;
    *(float2*)(out + base + 128) = v2;
}

// ---------------- launch ----------------
extern "C" void kernel_launch(void* const* d_in, const int* in_sizes, int n_in,
                              void* d_out, int out_size)
{
    const float* x   = (const float*)d_in[0];
    const float* w1  = (const float*)d_in[1];
    const float* b1  = (const float*)d_in[2];
    const float* w2  = (const float*)d_in[3];
    const float* b2  = (const float*)d_in[4];
    const float* pe  = (const float*)d_in[5];
    const float* wq  = (const float*)d_in[6];
    const float* wk  = (const float*)d_in[7];
    const float* wv  = (const float*)d_in[8];
    const float* lnw = (const float*)d_in[9];
    const float* lnb = (const float*)d_in[10];
    float* out = (float*)d_out;

    static int attr_set = 0;
    if (!attr_set) {
        cudaFuncSetAttribute(k_conv2, cudaFuncAttributeMaxDynamicSharedMemorySize, CONV_SMEM);
        attr_set = 1;
    }

    k_wprep<<<3, 256>>>(wq, wk, wv);
    k_conv2<<<dim3(64, BATCH), 256, CONV_SMEM>>>(x, w1, b1, w2, b2, pe);
    k_pad<<<1, BATCH * DM>>>(pe);
    k_qkv4<<<dim3((NROWS + 127) / 128, 3), 256>>>();
    k_prep<<<dim3(NTK, BATCH * NH), 128>>>();
    k_flash6<<<dim3(SMAX / 128, BATCH * NH), 128>>>();
    k_stats2<<<BATCH * SMAX / 8, 256>>>();
    k_out2<<<dim3(2, 64, BATCH * 20), 256>>>(lnw, lnb, out);
}